// round 2
// baseline (speedup 1.0000x reference)
#include <cuda_runtime.h>

#define B_  4
#define T_  2048
#define C_  768
#define NH  12
#define HS  64

// Scratch (no cudaMalloc allowed): qkv [B,T,3C] and pre-proj y [B,T,C]
__device__ float g_qkv[B_ * T_ * 3 * C_];   // 75.5 MB
__device__ float g_y  [B_ * T_ * C_];       // 25.2 MB

// ---------------------------------------------------------------------------
// fp32 SIMT GEMM: C[M,N] = A[M,K] @ B[K,N] + bias[N]
// BM=BN=128, BK=16, 256 threads, 8x8 micro-tile per thread (strided mapping).
// ---------------------------------------------------------------------------
__global__ __launch_bounds__(256) void sgemm_bias(
    const float* __restrict__ A, const float* __restrict__ B,
    const float* __restrict__ bias, float* __restrict__ C,
    int M, int N, int K)
{
    __shared__ float As[16][128];   // transposed: As[k][m]
    __shared__ float Bs[16][128];   // Bs[k][n]

    const int tid = threadIdx.x;
    const int tx = tid & 15;        // 0..15 -> n
    const int ty = tid >> 4;        // 0..15 -> m
    const int bm = blockIdx.y * 128;
    const int bn = blockIdx.x * 128;

    float acc[8][8];
#pragma unroll
    for (int i = 0; i < 8; i++)
#pragma unroll
        for (int j = 0; j < 8; j++) acc[i][j] = 0.0f;

    for (int k0 = 0; k0 < K; k0 += 16) {
        // Load A tile (128x16) transposed, B tile (16x128). 512 float4 each.
#pragma unroll
        for (int t = 0; t < 2; t++) {
            int idx = tid + t * 256;
            int arow = idx >> 2, ac4 = idx & 3;
            float4 av = *reinterpret_cast<const float4*>(
                A + (size_t)(bm + arow) * K + k0 + ac4 * 4);
            As[ac4 * 4 + 0][arow] = av.x;
            As[ac4 * 4 + 1][arow] = av.y;
            As[ac4 * 4 + 2][arow] = av.z;
            As[ac4 * 4 + 3][arow] = av.w;

            int brow = idx >> 5, bc4 = idx & 31;
            float4 bv = *reinterpret_cast<const float4*>(
                B + (size_t)(k0 + brow) * N + bn + bc4 * 4);
            *reinterpret_cast<float4*>(&Bs[brow][bc4 * 4]) = bv;
        }
        __syncthreads();

#pragma unroll
        for (int kk = 0; kk < 16; kk++) {
            float ra[8], rb[8];
#pragma unroll
            for (int i = 0; i < 8; i++) ra[i] = As[kk][ty + 16 * i];
#pragma unroll
            for (int j = 0; j < 8; j++) rb[j] = Bs[kk][tx + 16 * j];
#pragma unroll
            for (int i = 0; i < 8; i++)
#pragma unroll
                for (int j = 0; j < 8; j++)
                    acc[i][j] += ra[i] * rb[j];
        }
        __syncthreads();
    }

#pragma unroll
    for (int i = 0; i < 8; i++) {
        int row = bm + ty + 16 * i;
#pragma unroll
        for (int j = 0; j < 8; j++) {
            int col = bn + tx + 16 * j;
            C[(size_t)row * N + col] = acc[i][j] + bias[col];
        }
    }
}

// ---------------------------------------------------------------------------
// Flash attention, fp32. One block = 64 queries of one (b,h).
// 128 threads as 16(tr) x 8(tc). Thread owns S rows r=tr+16i (i<4),
// cols c=tc+8j (j<8) -- strided so inner-loop LDS are conflict-free.
// Row softmax reduced over the 8-lane group (same tr) via shfl width 8.
// ---------------------------------------------------------------------------
#define PITCH 68   // 64 + 4 pad

__global__ __launch_bounds__(128) void attn_kernel(
    const float* __restrict__ qkv, float* __restrict__ y)
{
    extern __shared__ float sm[];
    float* Qs = sm;
    float* Ks = sm + 64 * PITCH;
    float* Vs = sm + 2 * 64 * PITCH;
    float* Ps = sm + 3 * 64 * PITCH;

    const int qi = blockIdx.x;   // query tile (64 rows)
    const int h  = blockIdx.y;
    const int b  = blockIdx.z;
    const int tid = threadIdx.x;
    const int tr = tid >> 3;     // 0..15
    const int tc = tid & 7;      // 0..7
    const int q0 = qi * 64;

    const float* qb = qkv + (size_t)b * T_ * 3 * C_ + h * HS;
    const float* kb = qb + C_;
    const float* vb = qb + 2 * C_;

    // Load Q tile [64 x 64]
    for (int idx = tid; idx < 64 * 16; idx += 128) {
        int row = idx >> 4, c4 = idx & 15;
        float4 v = *reinterpret_cast<const float4*>(
            qb + (size_t)(q0 + row) * (3 * C_) + c4 * 4);
        float* d = Qs + row * PITCH + c4 * 4;
        d[0] = v.x; d[1] = v.y; d[2] = v.z; d[3] = v.w;
    }

    float m_i[4], l_i[4], o[4][8];
#pragma unroll
    for (int i = 0; i < 4; i++) {
        m_i[i] = -1e30f; l_i[i] = 0.0f;
#pragma unroll
        for (int j = 0; j < 8; j++) o[i][j] = 0.0f;
    }

    for (int jt = 0; jt <= qi; jt++) {
        const int k0 = jt * 64;
        __syncthreads();   // protect Vs/Ps reads of previous iteration

        // Load K and V tiles [64 x 64]
        for (int idx = tid; idx < 64 * 16; idx += 128) {
            int row = idx >> 4, c4 = idx & 15;
            float4 kv = *reinterpret_cast<const float4*>(
                kb + (size_t)(k0 + row) * (3 * C_) + c4 * 4);
            float* d = Ks + row * PITCH + c4 * 4;
            d[0] = kv.x; d[1] = kv.y; d[2] = kv.z; d[3] = kv.w;
            float4 vv = *reinterpret_cast<const float4*>(
                vb + (size_t)(k0 + row) * (3 * C_) + c4 * 4);
            d = Vs + row * PITCH + c4 * 4;
            d[0] = vv.x; d[1] = vv.y; d[2] = vv.z; d[3] = vv.w;
        }
        __syncthreads();

        // S = Q @ K^T  (4x8 per thread)
        float acc[4][8];
#pragma unroll
        for (int i = 0; i < 4; i++)
#pragma unroll
            for (int j = 0; j < 8; j++) acc[i][j] = 0.0f;

#pragma unroll 8
        for (int kk = 0; kk < 64; kk++) {
            float qr[4], kr[8];
#pragma unroll
            for (int i = 0; i < 4; i++) qr[i] = Qs[(tr + 16 * i) * PITCH + kk];
#pragma unroll
            for (int j = 0; j < 8; j++) kr[j] = Ks[(tc + 8 * j) * PITCH + kk];
#pragma unroll
            for (int i = 0; i < 4; i++)
#pragma unroll
                for (int j = 0; j < 8; j++)
                    acc[i][j] += qr[i] * kr[j];
        }

        // Online softmax (scale, causal mask, row-max/sum over 8-lane group)
#pragma unroll
        for (int i = 0; i < 4; i++) {
            const int r = q0 + tr + 16 * i;
            float rmax = -1e30f;
#pragma unroll
            for (int j = 0; j < 8; j++) {
                float s = acc[i][j] * 0.125f;
                if (k0 + tc + 8 * j > r) s = -1e30f;
                acc[i][j] = s;
                rmax = fmaxf(rmax, s);
            }
            rmax = fmaxf(rmax, __shfl_xor_sync(0xffffffffu, rmax, 1, 8));
            rmax = fmaxf(rmax, __shfl_xor_sync(0xffffffffu, rmax, 2, 8));
            rmax = fmaxf(rmax, __shfl_xor_sync(0xffffffffu, rmax, 4, 8));

            const float mnew  = fmaxf(m_i[i], rmax);
            const float alpha = __expf(m_i[i] - mnew);
            float rsum = 0.0f;
#pragma unroll
            for (int j = 0; j < 8; j++) {
                float p = __expf(acc[i][j] - mnew);
                rsum += p;
                Ps[(tr + 16 * i) * PITCH + tc + 8 * j] = p;
            }
            rsum += __shfl_xor_sync(0xffffffffu, rsum, 1, 8);
            rsum += __shfl_xor_sync(0xffffffffu, rsum, 2, 8);
            rsum += __shfl_xor_sync(0xffffffffu, rsum, 4, 8);

            l_i[i] = l_i[i] * alpha + rsum;
            m_i[i] = mnew;
#pragma unroll
            for (int j = 0; j < 8; j++) o[i][j] *= alpha;
        }
        __syncthreads();

        // O += P @ V
#pragma unroll 8
        for (int kk = 0; kk < 64; kk++) {
            float pr[4], vr[8];
#pragma unroll
            for (int i = 0; i < 4; i++) pr[i] = Ps[(tr + 16 * i) * PITCH + kk];
#pragma unroll
            for (int j = 0; j < 8; j++) vr[j] = Vs[kk * PITCH + tc + 8 * j];
#pragma unroll
            for (int i = 0; i < 4; i++)
#pragma unroll
                for (int j = 0; j < 8; j++)
                    o[i][j] += pr[i] * vr[j];
        }
    }

    // Normalize and write y[b, q, h*HS + d]
#pragma unroll
    for (int i = 0; i < 4; i++) {
        const float inv = 1.0f / l_i[i];
        const int row = q0 + tr + 16 * i;
#pragma unroll
        for (int j = 0; j < 8; j++) {
            y[((size_t)b * T_ + row) * C_ + h * HS + tc + 8 * j] = o[i][j] * inv;
        }
    }
}

// ---------------------------------------------------------------------------
extern "C" void kernel_launch(void* const* d_in, const int* in_sizes, int n_in,
                              void* d_out, int out_size)
{
    const float* x      = (const float*)d_in[0];
    const float* w_attn = (const float*)d_in[1];
    const float* b_attn = (const float*)d_in[2];
    const float* w_proj = (const float*)d_in[3];
    const float* b_proj = (const float*)d_in[4];
    float* out = (float*)d_out;

    float *qkv = nullptr, *y = nullptr;
    cudaGetSymbolAddress((void**)&qkv, g_qkv);
    cudaGetSymbolAddress((void**)&y,   g_y);

    const int smem_attn = 4 * 64 * PITCH * sizeof(float);  // 69632 B
    cudaFuncSetAttribute(attn_kernel,
                         cudaFuncAttributeMaxDynamicSharedMemorySize, smem_attn);

    // 1) QKV = x @ w_attn + b_attn      [8192 x 2304]
    dim3 g1(3 * C_ / 128, (B_ * T_) / 128);
    sgemm_bias<<<g1, 256>>>(x, w_attn, b_attn, qkv, B_ * T_, 3 * C_, C_);

    // 2) causal flash attention -> y   [8192 x 768]
    dim3 g2(T_ / 64, NH, B_);
    attn_kernel<<<g2, 128, smem_attn>>>(qkv, y);

    // 3) out = y @ w_proj + b_proj     [8192 x 768]
    dim3 g3(C_ / 128, (B_ * T_) / 128);
    sgemm_bias<<<g3, 256>>>(y, w_proj, b_proj, out, B_ * T_, C_, C_);
}

// round 7
// speedup vs baseline: 1.6401x; 1.6401x over previous
#include <cuda_runtime.h>
#include <cuda_bf16.h>
#include <cstdint>

#define B_  4
#define T_  2048
#define C_  768
#define NH  12
#define HS  64
#define M_  (B_ * T_)          // 8192
#define N1  (3 * C_)           // 2304
#define KD  C_                 // 768

// ---------------- scratch (__device__ globals; no cudaMalloc) --------------
__device__ float g_qkv[M_ * N1];          // 75.5 MB
__device__ float g_y  [M_ * C_];          // 25.2 MB
__device__ __align__(256) __nv_bfloat16 g_xh [M_ * KD], g_xl [M_ * KD];
__device__ __align__(256) __nv_bfloat16 g_yh [M_ * KD], g_yl [M_ * KD];
__device__ __align__(256) __nv_bfloat16 g_wah[N1 * KD], g_wal[N1 * KD]; // w_attn^T [N,K]
__device__ __align__(256) __nv_bfloat16 g_wph[C_ * KD], g_wpl[C_ * KD]; // w_proj^T [N,K]

// ---------------- helpers ---------------------------------------------------
__device__ __forceinline__ uint32_t smem_u32(const void* p) {
    uint32_t a;
    asm("{ .reg .u64 t; cvta.to.shared.u64 t, %1; cvt.u32.u64 %0, t; }"
        : "=r"(a) : "l"(p));
    return a;
}
__device__ __forceinline__ uint32_t swz(uint32_t off) {     // SW128
    return off ^ ((off >> 3) & 0x70);
}
__device__ __forceinline__ void cp16(uint32_t dst, const void* src) {
    asm volatile("cp.async.cg.shared.global [%0], [%1], 16;" :: "r"(dst), "l"(src));
}
#define CP_COMMIT() asm volatile("cp.async.commit_group;" ::: "memory")
#define CP_WAIT2()  asm volatile("cp.async.wait_group 2;" ::: "memory")

__device__ __forceinline__ void ldsm4(uint32_t& r0, uint32_t& r1,
                                      uint32_t& r2, uint32_t& r3, uint32_t a) {
    asm volatile("ldmatrix.sync.aligned.m8n8.x4.shared.b16 {%0,%1,%2,%3}, [%4];"
                 : "=r"(r0), "=r"(r1), "=r"(r2), "=r"(r3) : "r"(a));
}
__device__ __forceinline__ void mma16816(float* d, const uint32_t* a,
                                         const uint32_t* b) {
    asm volatile("mma.sync.aligned.m16n8k16.row.col.f32.bf16.bf16.f32 "
                 "{%0,%1,%2,%3}, {%4,%5,%6,%7}, {%8,%9}, {%0,%1,%2,%3};"
                 : "+f"(d[0]), "+f"(d[1]), "+f"(d[2]), "+f"(d[3])
                 : "r"(a[0]), "r"(a[1]), "r"(a[2]), "r"(a[3]),
                   "r"(b[0]), "r"(b[1]));
}

// ---------------- split conversion kernels ---------------------------------
__global__ __launch_bounds__(256) void split_cvt(
    const float* __restrict__ in, __nv_bfloat16* __restrict__ hi,
    __nv_bfloat16* __restrict__ lo, int n)
{
    int idx = (blockIdx.x * 256 + threadIdx.x) * 4;
    if (idx >= n) return;
    float4 v = *reinterpret_cast<const float4*>(in + idx);
    __nv_bfloat16 h0 = __float2bfloat16(v.x), h1 = __float2bfloat16(v.y);
    __nv_bfloat16 h2 = __float2bfloat16(v.z), h3 = __float2bfloat16(v.w);
    __nv_bfloat16 l0 = __float2bfloat16(v.x - __bfloat162float(h0));
    __nv_bfloat16 l1 = __float2bfloat16(v.y - __bfloat162float(h1));
    __nv_bfloat16 l2 = __float2bfloat16(v.z - __bfloat162float(h2));
    __nv_bfloat16 l3 = __float2bfloat16(v.w - __bfloat162float(h3));
    *reinterpret_cast<__nv_bfloat162*>(hi + idx)     = __nv_bfloat162(h0, h1);
    *reinterpret_cast<__nv_bfloat162*>(hi + idx + 2) = __nv_bfloat162(h2, h3);
    *reinterpret_cast<__nv_bfloat162*>(lo + idx)     = __nv_bfloat162(l0, l1);
    *reinterpret_cast<__nv_bfloat162*>(lo + idx + 2) = __nv_bfloat162(l2, l3);
}

// transpose + split: in [K,N] row-major -> hi/lo [N,K]
__global__ __launch_bounds__(256) void split_cvt_T(
    const float* __restrict__ in, __nv_bfloat16* __restrict__ hi,
    __nv_bfloat16* __restrict__ lo, int K, int N)
{
    __shared__ float t[32][33];
    const int tx = threadIdx.x & 31, ty = threadIdx.x >> 5;
    const int k0 = blockIdx.y * 32, n0 = blockIdx.x * 32;
#pragma unroll
    for (int r = 0; r < 32; r += 8)
        t[ty + r][tx] = in[(size_t)(k0 + ty + r) * N + n0 + tx];
    __syncthreads();
#pragma unroll
    for (int r = 0; r < 32; r += 8) {
        float v = t[tx][ty + r];              // k=k0+tx, n=n0+ty+r
        __nv_bfloat16 h = __float2bfloat16(v);
        __nv_bfloat16 l = __float2bfloat16(v - __bfloat162float(h));
        size_t o = (size_t)(n0 + ty + r) * K + k0 + tx;
        hi[o] = h; lo[o] = l;
    }
}

// ---------------- mma.sync split-bf16 GEMM ----------------------------------
// C[M,N] = A[M,K] @ Bt[N,K]^T + bias (fp32 out). 128x128 tile, BK=64,
// 8 warps (2x4), warp tile 64x32, 3-stage cp.async pipeline, SW128 smem.
#define GBK   64
#define TILEB (128 * 128)        // bytes: 128 rows x 128B (64 bf16)
#define STAGEB (4 * TILEB)       // Ah,Al,Bh,Bl  = 64KB
#define STAGES 3
#define GSMEM (STAGES * STAGEB)  // 192KB

__device__ __forceinline__ void load_op(
    const __nv_bfloat16* __restrict__ g, int row0, int K, int k0,
    uint32_t sdst, int tid)
{
#pragma unroll
    for (int t = 0; t < 4; t++) {
        int idx = tid + t * 256;             // 0..1023
        int row = idx >> 3, seg = idx & 7;
        const void* src = g + (size_t)(row0 + row) * K + k0 + seg * 8;
        cp16(sdst + swz(row * 128 + seg * 16), src);
    }
}

__global__ __launch_bounds__(256, 1) void gemm_mma(
    const __nv_bfloat16* __restrict__ Ah, const __nv_bfloat16* __restrict__ Al,
    const __nv_bfloat16* __restrict__ Bh, const __nv_bfloat16* __restrict__ Bl,
    const float* __restrict__ bias, float* __restrict__ Cmat,
    int M, int N, int K)
{
    extern __shared__ char smem[];
    const uint32_t sb = smem_u32(smem);
    const int tid  = threadIdx.x;
    const int wid  = tid >> 5, lane = tid & 31;
    const int bm = blockIdx.y * 128, bn = blockIdx.x * 128;
    const int wm = (wid >> 2) * 64, wn = (wid & 3) * 32;
    const int NC = K / GBK;                   // 12

    // prologue: stages 0..2
#pragma unroll
    for (int s = 0; s < STAGES; s++) {
        uint32_t st = sb + s * STAGEB;
        load_op(Ah, bm, K, s * GBK, st,             tid);
        load_op(Al, bm, K, s * GBK, st + TILEB,     tid);
        load_op(Bh, bn, K, s * GBK, st + 2 * TILEB, tid);
        load_op(Bl, bn, K, s * GBK, st + 3 * TILEB, tid);
        CP_COMMIT();
    }

    float acc[4][4][4];
#pragma unroll
    for (int i = 0; i < 4; i++)
#pragma unroll
        for (int j = 0; j < 4; j++)
#pragma unroll
            for (int r = 0; r < 4; r++) acc[i][j][r] = 0.0f;

    // per-lane ldmatrix row/seg bases
    const int arow = wm + (lane & 15);
    const int brow = wn + (lane & 7) + ((lane >> 4) & 1) * 8;

    for (int c = 0; c < NC; c++) {
        CP_WAIT2();
        __syncthreads();
        const uint32_t st = sb + (c % STAGES) * STAGEB;

#pragma unroll
        for (int ks = 0; ks < 4; ks++) {
            uint32_t ah[4][4], al[4][4], bh[4][2], bl[4][2];
            const uint32_t ka = (uint32_t)((ks * 2 + (lane >> 4)) * 16);
            const uint32_t kb = (uint32_t)((ks * 2 + ((lane >> 3) & 1)) * 16);
#pragma unroll
            for (int mi = 0; mi < 4; mi++) {
                uint32_t off = swz((uint32_t)(arow + mi * 16) * 128 + ka);
                ldsm4(ah[mi][0], ah[mi][1], ah[mi][2], ah[mi][3], st + off);
                ldsm4(al[mi][0], al[mi][1], al[mi][2], al[mi][3], st + TILEB + off);
            }
#pragma unroll
            for (int n2 = 0; n2 < 2; n2++) {
                uint32_t off = swz((uint32_t)(brow + n2 * 16) * 128 + kb);
                uint32_t r0, r1, r2, r3;
                ldsm4(r0, r1, r2, r3, st + 2 * TILEB + off);
                bh[2 * n2][0] = r0; bh[2 * n2][1] = r1;
                bh[2 * n2 + 1][0] = r2; bh[2 * n2 + 1][1] = r3;
                ldsm4(r0, r1, r2, r3, st + 3 * TILEB + off);
                bl[2 * n2][0] = r0; bl[2 * n2][1] = r1;
                bl[2 * n2 + 1][0] = r2; bl[2 * n2 + 1][1] = r3;
            }
#pragma unroll
            for (int mi = 0; mi < 4; mi++)
#pragma unroll
                for (int nj = 0; nj < 4; nj++) {
                    mma16816(acc[mi][nj], ah[mi], bh[nj]);
                    mma16816(acc[mi][nj], ah[mi], bl[nj]);
                    mma16816(acc[mi][nj], al[mi], bh[nj]);
                }
        }
        __syncthreads();

        if (c + STAGES < NC) {
            uint32_t nst = sb + (c % STAGES) * STAGEB;
            int k0 = (c + STAGES) * GBK;
            load_op(Ah, bm, K, k0, nst,             tid);
            load_op(Al, bm, K, k0, nst + TILEB,     tid);
            load_op(Bh, bn, K, k0, nst + 2 * TILEB, tid);
            load_op(Bl, bn, K, k0, nst + 3 * TILEB, tid);
        }
        CP_COMMIT();
    }

    // epilogue: acc frag -> C (+bias)
    const int r0 = bm + wm + (lane >> 2);
    const int c0 = bn + wn + (lane & 3) * 2;
#pragma unroll
    for (int mi = 0; mi < 4; mi++) {
        const int row = r0 + mi * 16;
#pragma unroll
        for (int nj = 0; nj < 4; nj++) {
            const int col = c0 + nj * 8;
            float2 bv = *reinterpret_cast<const float2*>(bias + col);
            float2 o0 = { acc[mi][nj][0] + bv.x, acc[mi][nj][1] + bv.y };
            float2 o1 = { acc[mi][nj][2] + bv.x, acc[mi][nj][3] + bv.y };
            *reinterpret_cast<float2*>(Cmat + (size_t)row * N + col)       = o0;
            *reinterpret_cast<float2*>(Cmat + (size_t)(row + 8) * N + col) = o1;
        }
    }
}

// ---------------- flash attention (fp32, unchanged) -------------------------
#define PITCH 68

__global__ __launch_bounds__(128) void attn_kernel(
    const float* __restrict__ qkv, float* __restrict__ y)
{
    extern __shared__ float sm[];
    float* Qs = sm;
    float* Ks = sm + 64 * PITCH;
    float* Vs = sm + 2 * 64 * PITCH;
    float* Ps = sm + 3 * 64 * PITCH;

    const int qi = blockIdx.x;
    const int h  = blockIdx.y;
    const int b  = blockIdx.z;
    const int tid = threadIdx.x;
    const int tr = tid >> 3;
    const int tc = tid & 7;
    const int q0 = qi * 64;

    const float* qb = qkv + (size_t)b * T_ * 3 * C_ + h * HS;
    const float* kb = qb + C_;
    const float* vb = qb + 2 * C_;

    for (int idx = tid; idx < 64 * 16; idx += 128) {
        int row = idx >> 4, c4 = idx & 15;
        float4 v = *reinterpret_cast<const float4*>(
            qb + (size_t)(q0 + row) * (3 * C_) + c4 * 4);
        float* d = Qs + row * PITCH + c4 * 4;
        d[0] = v.x; d[1] = v.y; d[2] = v.z; d[3] = v.w;
    }

    float m_i[4], l_i[4], o[4][8];
#pragma unroll
    for (int i = 0; i < 4; i++) {
        m_i[i] = -1e30f; l_i[i] = 0.0f;
#pragma unroll
        for (int j = 0; j < 8; j++) o[i][j] = 0.0f;
    }

    for (int jt = 0; jt <= qi; jt++) {
        const int k0 = jt * 64;
        __syncthreads();

        for (int idx = tid; idx < 64 * 16; idx += 128) {
            int row = idx >> 4, c4 = idx & 15;
            float4 kv = *reinterpret_cast<const float4*>(
                kb + (size_t)(k0 + row) * (3 * C_) + c4 * 4);
            float* d = Ks + row * PITCH + c4 * 4;
            d[0] = kv.x; d[1] = kv.y; d[2] = kv.z; d[3] = kv.w;
            float4 vv = *reinterpret_cast<const float4*>(
                vb + (size_t)(k0 + row) * (3 * C_) + c4 * 4);
            d = Vs + row * PITCH + c4 * 4;
            d[0] = vv.x; d[1] = vv.y; d[2] = vv.z; d[3] = vv.w;
        }
        __syncthreads();

        float acc[4][8];
#pragma unroll
        for (int i = 0; i < 4; i++)
#pragma unroll
            for (int j = 0; j < 8; j++) acc[i][j] = 0.0f;

#pragma unroll 8
        for (int kk = 0; kk < 64; kk++) {
            float qr[4], kr[8];
#pragma unroll
            for (int i = 0; i < 4; i++) qr[i] = Qs[(tr + 16 * i) * PITCH + kk];
#pragma unroll
            for (int j = 0; j < 8; j++) kr[j] = Ks[(tc + 8 * j) * PITCH + kk];
#pragma unroll
            for (int i = 0; i < 4; i++)
#pragma unroll
                for (int j = 0; j < 8; j++)
                    acc[i][j] += qr[i] * kr[j];
        }

#pragma unroll
        for (int i = 0; i < 4; i++) {
            const int r = q0 + tr + 16 * i;
            float rmax = -1e30f;
#pragma unroll
            for (int j = 0; j < 8; j++) {
                float s = acc[i][j] * 0.125f;
                if (k0 + tc + 8 * j > r) s = -1e30f;
                acc[i][j] = s;
                rmax = fmaxf(rmax, s);
            }
            rmax = fmaxf(rmax, __shfl_xor_sync(0xffffffffu, rmax, 1, 8));
            rmax = fmaxf(rmax, __shfl_xor_sync(0xffffffffu, rmax, 2, 8));
            rmax = fmaxf(rmax, __shfl_xor_sync(0xffffffffu, rmax, 4, 8));

            const float mnew  = fmaxf(m_i[i], rmax);
            const float alpha = __expf(m_i[i] - mnew);
            float rsum = 0.0f;
#pragma unroll
            for (int j = 0; j < 8; j++) {
                float p = __expf(acc[i][j] - mnew);
                rsum += p;
                Ps[(tr + 16 * i) * PITCH + tc + 8 * j] = p;
            }
            rsum += __shfl_xor_sync(0xffffffffu, rsum, 1, 8);
            rsum += __shfl_xor_sync(0xffffffffu, rsum, 2, 8);
            rsum += __shfl_xor_sync(0xffffffffu, rsum, 4, 8);

            l_i[i] = l_i[i] * alpha + rsum;
            m_i[i] = mnew;
#pragma unroll
            for (int j = 0; j < 8; j++) o[i][j] *= alpha;
        }
        __syncthreads();

#pragma unroll 8
        for (int kk = 0; kk < 64; kk++) {
            float pr[4], vr[8];
#pragma unroll
            for (int i = 0; i < 4; i++) pr[i] = Ps[(tr + 16 * i) * PITCH + kk];
#pragma unroll
            for (int j = 0; j < 8; j++) vr[j] = Vs[kk * PITCH + tc + 8 * j];
#pragma unroll
            for (int i = 0; i < 4; i++)
#pragma unroll
                for (int j = 0; j < 8; j++)
                    o[i][j] += pr[i] * vr[j];
        }
    }

#pragma unroll
    for (int i = 0; i < 4; i++) {
        const float inv = 1.0f / l_i[i];
        const int row = q0 + tr + 16 * i;
#pragma unroll
        for (int j = 0; j < 8; j++) {
            y[((size_t)b * T_ + row) * C_ + h * HS + tc + 8 * j] = o[i][j] * inv;
        }
    }
}

// ---------------------------------------------------------------------------
extern "C" void kernel_launch(void* const* d_in, const int* in_sizes, int n_in,
                              void* d_out, int out_size)
{
    const float* x      = (const float*)d_in[0];
    const float* w_attn = (const float*)d_in[1];
    const float* b_attn = (const float*)d_in[2];
    const float* w_proj = (const float*)d_in[3];
    const float* b_proj = (const float*)d_in[4];
    float* out = (float*)d_out;

    float *qkv, *y;
    __nv_bfloat16 *xh, *xl, *yh, *yl, *wah, *wal, *wph, *wpl;
    cudaGetSymbolAddress((void**)&qkv, g_qkv);
    cudaGetSymbolAddress((void**)&y,   g_y);
    cudaGetSymbolAddress((void**)&xh,  g_xh);
    cudaGetSymbolAddress((void**)&xl,  g_xl);
    cudaGetSymbolAddress((void**)&yh,  g_yh);
    cudaGetSymbolAddress((void**)&yl,  g_yl);
    cudaGetSymbolAddress((void**)&wah, g_wah);
    cudaGetSymbolAddress((void**)&wal, g_wal);
    cudaGetSymbolAddress((void**)&wph, g_wph);
    cudaGetSymbolAddress((void**)&wpl, g_wpl);

    cudaFuncSetAttribute(gemm_mma, cudaFuncAttributeMaxDynamicSharedMemorySize, GSMEM);
    const int smem_attn = 4 * 64 * PITCH * sizeof(float);
    cudaFuncSetAttribute(attn_kernel, cudaFuncAttributeMaxDynamicSharedMemorySize, smem_attn);

    // split conversions
    split_cvt<<<(M_ * KD) / (256 * 4), 256>>>(x, xh, xl, M_ * KD);
    split_cvt_T<<<dim3(N1 / 32, KD / 32), 256>>>(w_attn, wah, wal, KD, N1);
    split_cvt_T<<<dim3(C_ / 32, KD / 32), 256>>>(w_proj, wph, wpl, KD, C_);

    // 1) QKV = x @ w_attn + b_attn   [8192 x 2304]
    gemm_mma<<<dim3(N1 / 128, M_ / 128), 256, GSMEM>>>(
        xh, xl, wah, wal, b_attn, qkv, M_, N1, KD);

    // 2) causal flash attention -> y [8192 x 768]
    attn_kernel<<<dim3(T_ / 64, NH, B_), 128, smem_attn>>>(qkv, y);

    // 3) out = y @ w_proj + b_proj   [8192 x 768]
    split_cvt<<<(M_ * KD) / (256 * 4), 256>>>(y, yh, yl, M_ * KD);
    gemm_mma<<<dim3(C_ / 128, M_ / 128), 256, GSMEM>>>(
        yh, yl, wph, wpl, b_proj, out, M_, C_, KD);
}

// round 10
// speedup vs baseline: 2.9229x; 1.7821x over previous
#include <cuda_runtime.h>
#include <cuda_bf16.h>
#include <cstdint>

#define B_  4
#define T_  2048
#define C_  768
#define NH  12
#define HS  64
#define M_  (B_ * T_)          // 8192
#define N1  (3 * C_)           // 2304
#define KD  C_                 // 768
#define C3  (3 * C_)

// ---------------- scratch (__device__ globals; no cudaMalloc) --------------
__device__ __align__(256) __nv_bfloat16 g_xh  [M_ * KD], g_xl  [M_ * KD];
__device__ __align__(256) __nv_bfloat16 g_qkvh[M_ * N1], g_qkvl[M_ * N1];
__device__ __align__(256) __nv_bfloat16 g_yh  [M_ * KD], g_yl  [M_ * KD];
__device__ __align__(256) __nv_bfloat16 g_wah [N1 * KD], g_wal [N1 * KD];  // w_attn^T [N,K]
__device__ __align__(256) __nv_bfloat16 g_wph [C_ * KD], g_wpl [C_ * KD];  // w_proj^T [N,K]

// ---------------- helpers ---------------------------------------------------
__device__ __forceinline__ uint32_t smem_u32(const void* p) {
    uint32_t a;
    asm("{ .reg .u64 t; cvta.to.shared.u64 t, %1; cvt.u32.u64 %0, t; }"
        : "=r"(a) : "l"(p));
    return a;
}
__device__ __forceinline__ uint32_t swz(uint32_t off) {     // SW128
    return off ^ ((off >> 3) & 0x70);
}
__device__ __forceinline__ void cp16(uint32_t dst, const void* src) {
    asm volatile("cp.async.cg.shared.global [%0], [%1], 16;" :: "r"(dst), "l"(src));
}
#define CP_COMMIT() asm volatile("cp.async.commit_group;" ::: "memory")
#define CP_WAIT2()  asm volatile("cp.async.wait_group 2;" ::: "memory")
#define CP_WAIT1()  asm volatile("cp.async.wait_group 1;" ::: "memory")

__device__ __forceinline__ void ldsm4(uint32_t& r0, uint32_t& r1,
                                      uint32_t& r2, uint32_t& r3, uint32_t a) {
    asm volatile("ldmatrix.sync.aligned.m8n8.x4.shared.b16 {%0,%1,%2,%3}, [%4];"
                 : "=r"(r0), "=r"(r1), "=r"(r2), "=r"(r3) : "r"(a));
}
__device__ __forceinline__ void ldsm4t(uint32_t& r0, uint32_t& r1,
                                       uint32_t& r2, uint32_t& r3, uint32_t a) {
    asm volatile("ldmatrix.sync.aligned.m8n8.x4.trans.shared.b16 {%0,%1,%2,%3}, [%4];"
                 : "=r"(r0), "=r"(r1), "=r"(r2), "=r"(r3) : "r"(a));
}
__device__ __forceinline__ void mma16816(float* d, const uint32_t* a,
                                         const uint32_t* b) {
    asm volatile("mma.sync.aligned.m16n8k16.row.col.f32.bf16.bf16.f32 "
                 "{%0,%1,%2,%3}, {%4,%5,%6,%7}, {%8,%9}, {%0,%1,%2,%3};"
                 : "+f"(d[0]), "+f"(d[1]), "+f"(d[2]), "+f"(d[3])
                 : "r"(a[0]), "r"(a[1]), "r"(a[2]), "r"(a[3]),
                   "r"(b[0]), "r"(b[1]));
}
__device__ __forceinline__ float ex2f(float x) {
    float y; asm("ex2.approx.f32 %0, %1;" : "=f"(y) : "f"(x)); return y;
}
__device__ __forceinline__ void split_pack(float a, float b,
                                           uint32_t& hi, uint32_t& lo) {
    __nv_bfloat16 ha = __float2bfloat16(a), hb = __float2bfloat16(b);
    __nv_bfloat16 la = __float2bfloat16(a - __bfloat162float(ha));
    __nv_bfloat16 lb = __float2bfloat16(b - __bfloat162float(hb));
    __nv_bfloat162 H(ha, hb), L(la, lb);
    hi = *reinterpret_cast<uint32_t*>(&H);
    lo = *reinterpret_cast<uint32_t*>(&L);
}

// ---------------- split conversion kernels ---------------------------------
__global__ __launch_bounds__(256) void split_cvt(
    const float* __restrict__ in, __nv_bfloat16* __restrict__ hi,
    __nv_bfloat16* __restrict__ lo, int n)
{
    int idx = (blockIdx.x * 256 + threadIdx.x) * 4;
    if (idx >= n) return;
    float4 v = *reinterpret_cast<const float4*>(in + idx);
    __nv_bfloat16 h0 = __float2bfloat16(v.x), h1 = __float2bfloat16(v.y);
    __nv_bfloat16 h2 = __float2bfloat16(v.z), h3 = __float2bfloat16(v.w);
    __nv_bfloat16 l0 = __float2bfloat16(v.x - __bfloat162float(h0));
    __nv_bfloat16 l1 = __float2bfloat16(v.y - __bfloat162float(h1));
    __nv_bfloat16 l2 = __float2bfloat16(v.z - __bfloat162float(h2));
    __nv_bfloat16 l3 = __float2bfloat16(v.w - __bfloat162float(h3));
    *reinterpret_cast<__nv_bfloat162*>(hi + idx)     = __nv_bfloat162(h0, h1);
    *reinterpret_cast<__nv_bfloat162*>(hi + idx + 2) = __nv_bfloat162(h2, h3);
    *reinterpret_cast<__nv_bfloat162*>(lo + idx)     = __nv_bfloat162(l0, l1);
    *reinterpret_cast<__nv_bfloat162*>(lo + idx + 2) = __nv_bfloat162(l2, l3);
}

// transpose + split: in [K,N] row-major -> hi/lo [N,K]
__global__ __launch_bounds__(256) void split_cvt_T(
    const float* __restrict__ in, __nv_bfloat16* __restrict__ hi,
    __nv_bfloat16* __restrict__ lo, int K, int N)
{
    __shared__ float t[32][33];
    const int tx = threadIdx.x & 31, ty = threadIdx.x >> 5;
    const int k0 = blockIdx.y * 32, n0 = blockIdx.x * 32;
#pragma unroll
    for (int r = 0; r < 32; r += 8)
        t[ty + r][tx] = in[(size_t)(k0 + ty + r) * N + n0 + tx];
    __syncthreads();
#pragma unroll
    for (int r = 0; r < 32; r += 8) {
        float v = t[tx][ty + r];
        __nv_bfloat16 h = __float2bfloat16(v);
        __nv_bfloat16 l = __float2bfloat16(v - __bfloat162float(h));
        size_t o = (size_t)(n0 + ty + r) * K + k0 + tx;
        hi[o] = h; lo[o] = l;
    }
}

// ---------------- mma.sync split-bf16 GEMM ----------------------------------
#define GBK   64
#define TILEB (128 * 128)
#define STAGEB (4 * TILEB)
#define STAGES 3
#define GSMEM (STAGES * STAGEB)  // 192KB

__device__ __forceinline__ void load_op(
    const __nv_bfloat16* __restrict__ g, int row0, int K, int k0,
    uint32_t sdst, int tid)
{
#pragma unroll
    for (int t = 0; t < 4; t++) {
        int idx = tid + t * 256;
        int row = idx >> 3, seg = idx & 7;
        const void* src = g + (size_t)(row0 + row) * K + k0 + seg * 8;
        cp16(sdst + swz(row * 128 + seg * 16), src);
    }
}

template<bool SPLIT>
__global__ __launch_bounds__(256, 1) void gemm_mma(
    const __nv_bfloat16* __restrict__ Ah, const __nv_bfloat16* __restrict__ Al,
    const __nv_bfloat16* __restrict__ Bh, const __nv_bfloat16* __restrict__ Bl,
    const float* __restrict__ bias, float* __restrict__ Cf,
    __nv_bfloat16* __restrict__ Ch, __nv_bfloat16* __restrict__ Cl,
    int M, int N, int K)
{
    extern __shared__ char smem[];
    const uint32_t sb = smem_u32(smem);
    const int tid  = threadIdx.x;
    const int wid  = tid >> 5, lane = tid & 31;
    const int bm = blockIdx.y * 128, bn = blockIdx.x * 128;
    const int wm = (wid >> 2) * 64, wn = (wid & 3) * 32;
    const int NC = K / GBK;

#pragma unroll
    for (int s = 0; s < STAGES; s++) {
        uint32_t st = sb + s * STAGEB;
        load_op(Ah, bm, K, s * GBK, st,             tid);
        load_op(Al, bm, K, s * GBK, st + TILEB,     tid);
        load_op(Bh, bn, K, s * GBK, st + 2 * TILEB, tid);
        load_op(Bl, bn, K, s * GBK, st + 3 * TILEB, tid);
        CP_COMMIT();
    }

    float acc[4][4][4];
#pragma unroll
    for (int i = 0; i < 4; i++)
#pragma unroll
        for (int j = 0; j < 4; j++)
#pragma unroll
            for (int r = 0; r < 4; r++) acc[i][j][r] = 0.0f;

    const int arow = wm + (lane & 15);
    const int brow = wn + (lane & 7) + ((lane >> 4) & 1) * 8;

    for (int c = 0; c < NC; c++) {
        CP_WAIT2();
        __syncthreads();
        const uint32_t st = sb + (c % STAGES) * STAGEB;

#pragma unroll
        for (int ks = 0; ks < 4; ks++) {
            uint32_t ah[4][4], al[4][4], bh[4][2], bl[4][2];
            const uint32_t ka = (uint32_t)((ks * 2 + (lane >> 4)) * 16);
            const uint32_t kb = (uint32_t)((ks * 2 + ((lane >> 3) & 1)) * 16);
#pragma unroll
            for (int mi = 0; mi < 4; mi++) {
                uint32_t off = swz((uint32_t)(arow + mi * 16) * 128 + ka);
                ldsm4(ah[mi][0], ah[mi][1], ah[mi][2], ah[mi][3], st + off);
                ldsm4(al[mi][0], al[mi][1], al[mi][2], al[mi][3], st + TILEB + off);
            }
#pragma unroll
            for (int n2 = 0; n2 < 2; n2++) {
                uint32_t off = swz((uint32_t)(brow + n2 * 16) * 128 + kb);
                uint32_t r0, r1, r2, r3;
                ldsm4(r0, r1, r2, r3, st + 2 * TILEB + off);
                bh[2 * n2][0] = r0; bh[2 * n2][1] = r1;
                bh[2 * n2 + 1][0] = r2; bh[2 * n2 + 1][1] = r3;
                ldsm4(r0, r1, r2, r3, st + 3 * TILEB + off);
                bl[2 * n2][0] = r0; bl[2 * n2][1] = r1;
                bl[2 * n2 + 1][0] = r2; bl[2 * n2 + 1][1] = r3;
            }
#pragma unroll
            for (int mi = 0; mi < 4; mi++)
#pragma unroll
                for (int nj = 0; nj < 4; nj++) {
                    mma16816(acc[mi][nj], ah[mi], bh[nj]);
                    mma16816(acc[mi][nj], ah[mi], bl[nj]);
                    mma16816(acc[mi][nj], al[mi], bh[nj]);
                }
        }
        __syncthreads();

        if (c + STAGES < NC) {
            uint32_t nst = sb + (c % STAGES) * STAGEB;
            int k0 = (c + STAGES) * GBK;
            load_op(Ah, bm, K, k0, nst,             tid);
            load_op(Al, bm, K, k0, nst + TILEB,     tid);
            load_op(Bh, bn, K, k0, nst + 2 * TILEB, tid);
            load_op(Bl, bn, K, k0, nst + 3 * TILEB, tid);
        }
        CP_COMMIT();
    }

    const int r0 = bm + wm + (lane >> 2);
    const int c0 = bn + wn + (lane & 3) * 2;
#pragma unroll
    for (int mi = 0; mi < 4; mi++) {
        const int row = r0 + mi * 16;
#pragma unroll
        for (int nj = 0; nj < 4; nj++) {
            const int col = c0 + nj * 8;
            float2 bv = *reinterpret_cast<const float2*>(bias + col);
            float o0 = acc[mi][nj][0] + bv.x, o1 = acc[mi][nj][1] + bv.y;
            float o2 = acc[mi][nj][2] + bv.x, o3 = acc[mi][nj][3] + bv.y;
            if (SPLIT) {
                uint32_t h01, l01, h23, l23;
                split_pack(o0, o1, h01, l01);
                split_pack(o2, o3, h23, l23);
                *reinterpret_cast<uint32_t*>(Ch + (size_t)row * N + col)       = h01;
                *reinterpret_cast<uint32_t*>(Cl + (size_t)row * N + col)       = l01;
                *reinterpret_cast<uint32_t*>(Ch + (size_t)(row + 8) * N + col) = h23;
                *reinterpret_cast<uint32_t*>(Cl + (size_t)(row + 8) * N + col) = l23;
            } else {
                *reinterpret_cast<float2*>(Cf + (size_t)row * N + col)       = make_float2(o0, o1);
                *reinterpret_cast<float2*>(Cf + (size_t)(row + 8) * N + col) = make_float2(o2, o3);
            }
        }
    }
}

// ---------------- flash attention on mma.sync (split bf16) ------------------
// Block: 128 queries x one (b,h). 8 warps x 16 q rows. Key tiles of 64,
// double-buffered cp.async. S and PV both 3-term split, fp32 accumulators.
#define QH_OFF 0
#define QL_OFF (128 * 128)
#define ST_OFF (2 * 128 * 128)       // 32768
#define KHO 0
#define KLO 8192
#define VHO 16384
#define VLO 24576
#define ASTAGE 32768
#define ASMEM (ST_OFF + 2 * ASTAGE)  // 98304

__device__ __forceinline__ void load_kv_tile(
    const __nv_bfloat16* __restrict__ qh, const __nv_bfloat16* __restrict__ ql,
    size_t baseK, size_t baseV, int k0, uint32_t st, int tid)
{
#pragma unroll
    for (int t = 0; t < 2; t++) {
        int idx = tid + t * 256;
        int row = idx >> 3, seg = idx & 7;
        size_t gK = baseK + (size_t)(k0 + row) * C3 + seg * 8;
        size_t gV = baseV + (size_t)(k0 + row) * C3 + seg * 8;
        uint32_t off = swz(row * 128 + seg * 16);
        cp16(st + KHO + off, qh + gK);
        cp16(st + KLO + off, ql + gK);
        cp16(st + VHO + off, qh + gV);
        cp16(st + VLO + off, ql + gV);
    }
}

__global__ __launch_bounds__(256) void attn_mma(
    const __nv_bfloat16* __restrict__ qkvh, const __nv_bfloat16* __restrict__ qkvl,
    __nv_bfloat16* __restrict__ yh, __nv_bfloat16* __restrict__ yl)
{
    extern __shared__ char smem[];
    const uint32_t sb = smem_u32(smem);
    const int tid = threadIdx.x;
    const int w = tid >> 5, lane = tid & 31;
    const int qb = (T_ / 128 - 1) - blockIdx.x;   // reversed for balance
    const int h = blockIdx.y, b = blockIdx.z;
    const int q0 = qb * 128;
    const int NT = 2 * (qb + 1);
    const float SCL = 0.125f * 1.4426950408889634f;

    const size_t baseRow = (size_t)b * T_ * C3 + (size_t)h * HS;
    const size_t baseQ = baseRow;            // + q*C3
    const size_t baseK = baseRow + C_;
    const size_t baseV = baseRow + 2 * C_;

    // prologue: Q tile + stage 0, then stage 1
#pragma unroll
    for (int t = 0; t < 4; t++) {
        int idx = tid + t * 256;
        int row = idx >> 3, seg = idx & 7;
        size_t g = baseQ + (size_t)(q0 + row) * C3 + seg * 8;
        uint32_t off = swz(row * 128 + seg * 16);
        cp16(sb + QH_OFF + off, qkvh + g);
        cp16(sb + QL_OFF + off, qkvl + g);
    }
    load_kv_tile(qkvh, qkvl, baseK, baseV, 0, sb + ST_OFF, tid);
    CP_COMMIT();
    if (NT > 1) load_kv_tile(qkvh, qkvl, baseK, baseV, 64, sb + ST_OFF + ASTAGE, tid);
    CP_COMMIT();

    uint32_t qhf[4][4], qlf[4][4];
    float o[8][4];
#pragma unroll
    for (int i = 0; i < 8; i++)
#pragma unroll
        for (int r = 0; r < 4; r++) o[i][r] = 0.0f;
    float m0 = -1e30f, m1 = -1e30f, l0 = 0.0f, l1 = 0.0f;

    const int qrow_hi = q0 + w * 16 + 15;
    const int r0row = q0 + w * 16 + (lane >> 2);
    const int r1row = r0row + 8;

    for (int c = 0; c < NT; c++) {
        CP_WAIT1();
        __syncthreads();

        if (c == 0) {   // move Q to registers (a-fragments)
            const int arow = w * 16 + (lane & 15);
#pragma unroll
            for (int ks = 0; ks < 4; ks++) {
                uint32_t ka = (uint32_t)((ks * 2 + (lane >> 4)) * 16);
                uint32_t off = swz((uint32_t)arow * 128 + ka);
                ldsm4(qhf[ks][0], qhf[ks][1], qhf[ks][2], qhf[ks][3], sb + QH_OFF + off);
                ldsm4(qlf[ks][0], qlf[ks][1], qlf[ks][2], qlf[ks][3], sb + QL_OFF + off);
            }
        }

        const int k0 = c * 64;
        const uint32_t st = sb + ST_OFF + (c & 1) * ASTAGE;

        if (k0 <= qrow_hi) {
            // ---- S = Q @ K^T (split) ----
            float s[8][4];
#pragma unroll
            for (int i = 0; i < 8; i++)
#pragma unroll
                for (int r = 0; r < 4; r++) s[i][r] = 0.0f;

#pragma unroll
            for (int ks = 0; ks < 4; ks++) {
                uint32_t kh[8][2], kl[8][2];
                const uint32_t kb = (uint32_t)((ks * 2 + ((lane >> 3) & 1)) * 16);
                const int brow = (lane & 7) + ((lane >> 4) & 1) * 8;
#pragma unroll
                for (int ng = 0; ng < 4; ng++) {
                    uint32_t off = swz((uint32_t)(ng * 16 + brow) * 128 + kb);
                    uint32_t r0, r1, r2, r3;
                    ldsm4(r0, r1, r2, r3, st + KHO + off);
                    kh[2 * ng][0] = r0; kh[2 * ng][1] = r1;
                    kh[2 * ng + 1][0] = r2; kh[2 * ng + 1][1] = r3;
                    ldsm4(r0, r1, r2, r3, st + KLO + off);
                    kl[2 * ng][0] = r0; kl[2 * ng][1] = r1;
                    kl[2 * ng + 1][0] = r2; kl[2 * ng + 1][1] = r3;
                }
#pragma unroll
                for (int nb = 0; nb < 8; nb++) {
                    mma16816(s[nb], qhf[ks], kh[nb]);
                    mma16816(s[nb], qhf[ks], kl[nb]);
                    mma16816(s[nb], qlf[ks], kh[nb]);
                }
            }

            // ---- online softmax (scaled by log2e) ----
            const bool needmask = (k0 + 63 > q0 + w * 16);
            float mx0 = -1e30f, mx1 = -1e30f;
#pragma unroll
            for (int nb = 0; nb < 8; nb++) {
                float v0 = s[nb][0] * SCL, v1 = s[nb][1] * SCL;
                float v2 = s[nb][2] * SCL, v3 = s[nb][3] * SCL;
                if (needmask) {
                    int key = k0 + nb * 8 + 2 * (lane & 3);
                    if (key     > r0row) v0 = -1e30f;
                    if (key + 1 > r0row) v1 = -1e30f;
                    if (key     > r1row) v2 = -1e30f;
                    if (key + 1 > r1row) v3 = -1e30f;
                }
                s[nb][0] = v0; s[nb][1] = v1; s[nb][2] = v2; s[nb][3] = v3;
                mx0 = fmaxf(mx0, fmaxf(v0, v1));
                mx1 = fmaxf(mx1, fmaxf(v2, v3));
            }
            mx0 = fmaxf(mx0, __shfl_xor_sync(0xffffffffu, mx0, 1));
            mx0 = fmaxf(mx0, __shfl_xor_sync(0xffffffffu, mx0, 2));
            mx1 = fmaxf(mx1, __shfl_xor_sync(0xffffffffu, mx1, 1));
            mx1 = fmaxf(mx1, __shfl_xor_sync(0xffffffffu, mx1, 2));

            const float mn0 = fmaxf(m0, mx0), mn1 = fmaxf(m1, mx1);
            const float a0 = ex2f(m0 - mn0), a1 = ex2f(m1 - mn1);
            m0 = mn0; m1 = mn1;
            l0 *= a0; l1 *= a1;
#pragma unroll
            for (int nb = 0; nb < 8; nb++) {
                float p0 = ex2f(s[nb][0] - m0), p1 = ex2f(s[nb][1] - m0);
                float p2 = ex2f(s[nb][2] - m1), p3 = ex2f(s[nb][3] - m1);
                l0 += p0 + p1; l1 += p2 + p3;
                s[nb][0] = p0; s[nb][1] = p1; s[nb][2] = p2; s[nb][3] = p3;
            }
#pragma unroll
            for (int nd = 0; nd < 8; nd++) {
                o[nd][0] *= a0; o[nd][1] *= a0;
                o[nd][2] *= a1; o[nd][3] *= a1;
            }

            // ---- O += P @ V (split; P from regs, V via ldmatrix.trans) ----
#pragma unroll
            for (int kp = 0; kp < 4; kp++) {
                uint32_t pah[4], pal[4];
                split_pack(s[2 * kp][0],     s[2 * kp][1],     pah[0], pal[0]);
                split_pack(s[2 * kp][2],     s[2 * kp][3],     pah[1], pal[1]);
                split_pack(s[2 * kp + 1][0], s[2 * kp + 1][1], pah[2], pal[2]);
                split_pack(s[2 * kp + 1][2], s[2 * kp + 1][3], pah[3], pal[3]);

                uint32_t vh[8][2], vl[8][2];
                const uint32_t vrow = (uint32_t)(kp * 16 + (lane & 7) + ((lane >> 3) & 1) * 8);
#pragma unroll
                for (int dg = 0; dg < 4; dg++) {
                    uint32_t off = swz(vrow * 128 + dg * 32 + ((lane >> 4) & 1) * 16);
                    uint32_t r0, r1, r2, r3;
                    ldsm4t(r0, r1, r2, r3, st + VHO + off);
                    vh[2 * dg][0] = r0; vh[2 * dg][1] = r1;
                    vh[2 * dg + 1][0] = r2; vh[2 * dg + 1][1] = r3;
                    ldsm4t(r0, r1, r2, r3, st + VLO + off);
                    vl[2 * dg][0] = r0; vl[2 * dg][1] = r1;
                    vl[2 * dg + 1][0] = r2; vl[2 * dg + 1][1] = r3;
                }
#pragma unroll
                for (int nd = 0; nd < 8; nd++) {
                    mma16816(o[nd], pah, vh[nd]);
                    mma16816(o[nd], pah, vl[nd]);
                    mma16816(o[nd], pal, vh[nd]);
                }
            }
        }

        __syncthreads();
        if (c + 2 < NT)
            load_kv_tile(qkvh, qkvl, baseK, baseV, (c + 2) * 64,
                         sb + ST_OFF + (c & 1) * ASTAGE, tid);
        CP_COMMIT();
    }

    // ---- finalize: reduce l, normalize, write y hi/lo ----
    l0 += __shfl_xor_sync(0xffffffffu, l0, 1);
    l0 += __shfl_xor_sync(0xffffffffu, l0, 2);
    l1 += __shfl_xor_sync(0xffffffffu, l1, 1);
    l1 += __shfl_xor_sync(0xffffffffu, l1, 2);
    const float inv0 = 1.0f / l0, inv1 = 1.0f / l1;

    const size_t ybase = (size_t)b * T_ * C_ + (size_t)h * HS;
#pragma unroll
    for (int nd = 0; nd < 8; nd++) {
        int d = nd * 8 + 2 * (lane & 3);
        size_t i0 = ybase + (size_t)r0row * C_ + d;
        size_t i1 = ybase + (size_t)r1row * C_ + d;
        uint32_t hh, ll;
        split_pack(o[nd][0] * inv0, o[nd][1] * inv0, hh, ll);
        *reinterpret_cast<uint32_t*>(yh + i0) = hh;
        *reinterpret_cast<uint32_t*>(yl + i0) = ll;
        split_pack(o[nd][2] * inv1, o[nd][3] * inv1, hh, ll);
        *reinterpret_cast<uint32_t*>(yh + i1) = hh;
        *reinterpret_cast<uint32_t*>(yl + i1) = ll;
    }
}

// ---------------------------------------------------------------------------
extern "C" void kernel_launch(void* const* d_in, const int* in_sizes, int n_in,
                              void* d_out, int out_size)
{
    const float* x      = (const float*)d_in[0];
    const float* w_attn = (const float*)d_in[1];
    const float* b_attn = (const float*)d_in[2];
    const float* w_proj = (const float*)d_in[3];
    const float* b_proj = (const float*)d_in[4];
    float* out = (float*)d_out;

    __nv_bfloat16 *xh, *xl, *qkvh, *qkvl, *yh, *yl, *wah, *wal, *wph, *wpl;
    cudaGetSymbolAddress((void**)&xh,   g_xh);
    cudaGetSymbolAddress((void**)&xl,   g_xl);
    cudaGetSymbolAddress((void**)&qkvh, g_qkvh);
    cudaGetSymbolAddress((void**)&qkvl, g_qkvl);
    cudaGetSymbolAddress((void**)&yh,   g_yh);
    cudaGetSymbolAddress((void**)&yl,   g_yl);
    cudaGetSymbolAddress((void**)&wah,  g_wah);
    cudaGetSymbolAddress((void**)&wal,  g_wal);
    cudaGetSymbolAddress((void**)&wph,  g_wph);
    cudaGetSymbolAddress((void**)&wpl,  g_wpl);

    cudaFuncSetAttribute(gemm_mma<true>,  cudaFuncAttributeMaxDynamicSharedMemorySize, GSMEM);
    cudaFuncSetAttribute(gemm_mma<false>, cudaFuncAttributeMaxDynamicSharedMemorySize, GSMEM);
    cudaFuncSetAttribute(attn_mma, cudaFuncAttributeMaxDynamicSharedMemorySize, ASMEM);

    // split conversions (inputs only)
    split_cvt<<<(M_ * KD) / (256 * 4), 256>>>(x, xh, xl, M_ * KD);
    split_cvt_T<<<dim3(N1 / 32, KD / 32), 256>>>(w_attn, wah, wal, KD, N1);
    split_cvt_T<<<dim3(C_ / 32, KD / 32), 256>>>(w_proj, wph, wpl, KD, C_);

    // 1) QKV = x @ w_attn + b_attn -> split bf16 qkv  [8192 x 2304]
    gemm_mma<true><<<dim3(N1 / 128, M_ / 128), 256, GSMEM>>>(
        xh, xl, wah, wal, b_attn, nullptr, qkvh, qkvl, M_, N1, KD);

    // 2) causal flash attention -> split bf16 y  [8192 x 768]
    attn_mma<<<dim3(T_ / 128, NH, B_), 256, ASMEM>>>(qkvh, qkvl, yh, yl);

    // 3) out = y @ w_proj + b_proj  [8192 x 768] fp32
    gemm_mma<false><<<dim3(C_ / 128, M_ / 128), 256, GSMEM>>>(
        yh, yl, wph, wpl, b_proj, out, nullptr, nullptr, M_, C_, KD);
}